// round 8
// baseline (speedup 1.0000x reference)
#include <cuda_runtime.h>
#include <cstdint>
#include <math.h>

#define EPSV 1e-4f
#define BROWS 8192
#define FDIM 512
#define PDIM 64
#define CDIM 100
#define GROWS 32

typedef unsigned long long ull;

__device__ float g_si[BROWS * PDIM];
__device__ float g_u2[PDIM * 112];   // normalized beta^2, zero-padded rows

// ---- packed f32x2 helpers ----
__device__ __forceinline__ ull pk2(float lo, float hi) {
    ull r; asm("mov.b64 %0, {%1, %2};" : "=l"(r) : "f"(lo), "f"(hi)); return r;
}
__device__ __forceinline__ float2 upk2(ull v) {
    float2 r; asm("mov.b64 {%0, %1}, %2;" : "=f"(r.x), "=f"(r.y) : "l"(v)); return r;
}
__device__ __forceinline__ ull fma2(ull a, ull b, ull c) {
    ull d; asm("fma.rn.f32x2 %0, %1, %2, %3;" : "=l"(d) : "l"(a), "l"(b), "l"(c)); return d;
}
__device__ __forceinline__ ull mul2(ull a, ull b) {
    ull d; asm("mul.rn.f32x2 %0, %1, %2;" : "=l"(d) : "l"(a), "l"(b)); return d;
}
__device__ __forceinline__ ull add2(ull a, ull b) {
    ull d; asm("add.rn.f32x2 %0, %1, %2;" : "=l"(d) : "l"(a), "l"(b)); return d;
}
__device__ __forceinline__ float frcp(float x) {
    float r; asm("rcp.approx.f32 %0, %1;" : "=f"(r) : "f"(x)); return r;
}
__device__ __forceinline__ unsigned int s2u(const void* p) {
    return (unsigned int)__cvta_generic_to_shared(p);
}
__device__ __forceinline__ void cpa16(unsigned int dst, const void* src) {
    asm volatile("cp.async.cg.shared.global [%0], [%1], 16;" :: "r"(dst), "l"(src));
}

// ================= GEMM + si : 128 threads, tile 4 rows x 4 protos =========
// dyn smem (floats): XS[2][2048] @0, WS[2][4096] @4096, sWn @12288
#define GSM_BYTES (12352 * 4)

__device__ __forceinline__ void stage_chunk(float* dsm, int buf, int tid,
                                            const float* __restrict__ x,
                                            const float* __restrict__ w,
                                            int r0, int kc) {
    float* xsb = dsm + buf * 2048;
    float* wsb = dsm + 4096 + buf * 4096;
    #pragma unroll
    for (int it = 0; it < 4; it++) {
        int f = tid + it * 128;
        int row = f >> 4, c = f & 15;
        unsigned int dst = s2u(xsb + (row << 6) + ((c * 4) ^ (((row >> 2) & 15) << 2)));
        cpa16(dst, x + (size_t)(r0 + row) * FDIM + kc + c * 4);
    }
    #pragma unroll
    for (int it = 0; it < 8; it++) {
        int f = tid + it * 128;
        int p = f >> 4, c = f & 15;
        unsigned int dst = s2u(wsb + (p << 6) + ((c * 4) ^ (((p >> 2) & 15) << 2)));
        cpa16(dst, w + (size_t)p * FDIM + kc + c * 4);
    }
    asm volatile("cp.async.commit_group;" ::: "memory");
}

__global__ __launch_bounds__(128)
void gemm_si_kernel(const float* __restrict__ x, const float* __restrict__ w,
                    const float* __restrict__ xi, const float* __restrict__ eta,
                    const float* __restrict__ beta) {
    extern __shared__ __align__(16) float dsm[];
    const int tid = threadIdx.x;

    // extra block: compute u table once
    if (blockIdx.x == BROWS / GROWS) {
        if (tid < PDIM) {
            const float* br = beta + (size_t)tid * CDIM;
            float* ur = g_u2 + tid * 112;
            float s2 = 0.f;
            #pragma unroll 4
            for (int c = 0; c < CDIM; c++) { float v = br[c]; float bb = v * v; ur[c] = bb; s2 += bb; }
            float rs = 1.f / s2;
            #pragma unroll 4
            for (int c = 0; c < CDIM; c++) ur[c] *= rs;
            #pragma unroll
            for (int c = CDIM; c < 112; c++) ur[c] = 0.f;
        }
        return;
    }

    const int rg = tid >> 4;   // 0..7 : rows rg*4 + j
    const int pg = tid & 15;   // 0..15: protos pg*4 + i
    const int r0 = blockIdx.x * GROWS;
    float* sWn = dsm + 12288;

    // wnorm ownership (threads 0..63), bank-spread row mapping
    const int t64  = tid & 63;
    const int rw   = ((t64 & 15) << 2) | (t64 >> 4);
    const int xorW = (t64 & 15) << 2;

    ull acc[4][4];
    #pragma unroll
    for (int j = 0; j < 4; j++)
        #pragma unroll
        for (int i = 0; i < 4; i++) acc[j][i] = 0ull;
    ull xn2[4] = {0ull, 0ull, 0ull, 0ull};
    ull wn2 = 0ull;

    stage_chunk(dsm, 0, tid, x, w, r0, 0);

    #pragma unroll 1
    for (int ch = 0; ch < FDIM / 64; ch++) {
        const int buf = ch & 1;
        if (ch < FDIM / 64 - 1) {
            stage_chunk(dsm, buf ^ 1, tid, x, w, r0, (ch + 1) * 64);
            asm volatile("cp.async.wait_group 1;" ::: "memory");
        } else {
            asm volatile("cp.async.wait_group 0;" ::: "memory");
        }
        __syncthreads();

        const float* xb = dsm + buf * 2048;
        const float* wb = dsm + 4096 + buf * 4096;

        if (tid < PDIM) {   // wnorm partials from staged w
            const float* wr = wb + (rw << 6);
            #pragma unroll
            for (int c = 0; c < 16; c++) {
                ulonglong2 v = *(const ulonglong2*)(wr + ((c * 4) ^ xorW));
                wn2 = fma2(v.x, v.x, wn2);
                wn2 = fma2(v.y, v.y, wn2);
            }
        }

        #pragma unroll
        for (int kk = 0; kk < 64; kk += 4) {
            ulonglong2 a2[4], b2[4];
            #pragma unroll
            for (int j = 0; j < 4; j++)
                a2[j] = *(const ulonglong2*)(xb + ((rg * 4 + j) << 6) + (kk ^ (rg << 2)));
            #pragma unroll
            for (int i = 0; i < 4; i++)
                b2[i] = *(const ulonglong2*)(wb + ((pg * 4 + i) << 6) + (kk ^ (pg << 2)));
            #pragma unroll
            for (int j = 0; j < 4; j++) {
                xn2[j] = fma2(a2[j].x, a2[j].x, xn2[j]);
                xn2[j] = fma2(a2[j].y, a2[j].y, xn2[j]);
                #pragma unroll
                for (int i = 0; i < 4; i++) {
                    acc[j][i] = fma2(a2[j].x, b2[i].x, acc[j][i]);
                    acc[j][i] = fma2(a2[j].y, b2[i].y, acc[j][i]);
                }
            }
        }
        __syncthreads();
    }

    if (tid < PDIM) { float2 v = upk2(wn2); sWn[rw] = v.x + v.y; }
    __syncthreads();

    // per-thread gamma/alpha/wnorm for 4 protos
    float gam[4], alp[4], wnv[4];
    #pragma unroll
    for (int i = 0; i < 4; i++) {
        int p = pg * 4 + i;
        float e = __ldg(eta + p);
        gam[i] = e * e;
        alp[i] = 1.f / (1.f + __expf(-__ldg(xi + p)));
        wnv[i] = sWn[p];
    }

    const unsigned FULL = 0xffffffffu;
    #pragma unroll
    for (int j = 0; j < 4; j++) {
        const int row = rg * 4 + j;
        float2 xv = upk2(xn2[j]);
        const float xn = xv.x + xv.y;
        float sv[4];
        float mx = 0.f;
        #pragma unroll
        for (int i = 0; i < 4; i++) {
            float2 dv = upk2(acc[j][i]);
            float d = xn - 2.f * (dv.x + dv.y) + wnv[i];
            float si = __expf(-gam[i] * d) * alp[i];
            sv[i] = si;
            mx = fmaxf(mx, si);
        }
        // row-max across the 16 pg lanes (same rg = same half-warp)
        mx = fmaxf(mx, __shfl_xor_sync(FULL, mx, 1));
        mx = fmaxf(mx, __shfl_xor_sync(FULL, mx, 2));
        mx = fmaxf(mx, __shfl_xor_sync(FULL, mx, 4));
        mx = fmaxf(mx, __shfl_xor_sync(FULL, mx, 8));
        float inv = 1.f / (mx + EPSV);
        float4 o;
        o.x = sv[0] * inv; o.y = sv[1] * inv; o.z = sv[2] * inv; o.w = sv[3] * inv;
        *(float4*)(g_si + (size_t)(r0 + row) * PDIM + pg * 4) = o;
    }
}

// ================= Dempster scan : 1 row per 8-lane group, 256 threads ======
// Deferred normalization: rinv computed at p%4==2, folded into the scalar
// coefficients at p%4==0 (scale-equivariance makes this exact).
#define SSM_FLOATS (7168 + 32 * 68 + 32 * 102)

#define DS_STEP(P, APPLY, START) do {                                          \
    float s_ = srow[(P)];                                                      \
    float a_ = 1.f - s_;                                                       \
    if (APPLY) { s_ *= pend; a_ *= pend; }                                     \
    float g1_ = s_ * om;                                                       \
    om = 3.f * a_ * om;                                                        \
    ull sp_ = pk2(s_, s_), ap_ = pk2(a_, a_), gp_ = pk2(g1_, g1_);             \
    const float* up_ = sU + (P) * 112 + 2 * q;                                 \
    _Pragma("unroll")                                                          \
    for (int i_ = 0; i_ < 7; i_++) {                                           \
        ull u2_ = *(const ull*)(up_ + 16 * i_);                                \
        m[i_] = fma2(gp_, u2_, mul2(m[i_], fma2(sp_, u2_, ap_)));              \
    }                                                                          \
    m[6] = mul2(m[6], fix6);                                                   \
    if (START) {                                                               \
        ull ps_ = m[0];                                                        \
        _Pragma("unroll")                                                      \
        for (int i_ = 1; i_ < 7; i_++) ps_ = add2(ps_, m[i_]);                 \
        float2 pv_ = upk2(ps_);                                                \
        float pa_ = pv_.x + pv_.y;                                             \
        pa_ += __shfl_xor_sync(FULL, pa_, 1);                                  \
        pa_ += __shfl_xor_sync(FULL, pa_, 2);                                  \
        pa_ += __shfl_xor_sync(FULL, pa_, 4);                                  \
        pend = frcp(pa_);                                                      \
    }                                                                          \
} while (0)

__global__ __launch_bounds__(256)
void scan_kernel(float* __restrict__ out) {
    extern __shared__ __align__(16) float ssm[];
    float* sU   = ssm;                   // 7168 floats
    float* sSi  = ssm + 7168;            // 32 rows x stride 68
    float* sOut = ssm + 7168 + 32 * 68;  // 32 rows x stride 102

    const int tid = threadIdx.x;
    const int r0  = blockIdx.x * 32;
    const unsigned FULL = 0xffffffffu;

    #pragma unroll
    for (int it = 0; it < 7; it++) {
        int f = tid + it * 256;
        *(float4*)(sU + f * 4) = *(const float4*)(g_u2 + f * 4);
    }
    #pragma unroll
    for (int it = 0; it < 2; it++) {
        int f = tid + it * 256;
        int r = f >> 4, c = f & 15;
        *(float4*)(sSi + r * 68 + c * 4) =
            *(const float4*)(g_si + (size_t)(r0 + r) * PDIM + c * 4);
    }
    __syncthreads();

    const int lane = tid & 31;
    const int warp = tid >> 5;
    const int g = lane >> 3;
    const int q = lane & 7;            // pairs j = 2q + 16i
    const int r = warp * 4 + g;
    const float* srow = sSi + r * 68;

    const ull fix6 = pk2((q == 2) ? 3.f : 1.f, 1.f);

    ull m[7];
    float om, pend = 1.f;
    {
        float s0 = srow[0];
        ull s0p = pk2(s0, s0);
        const float* u0 = sU + 2 * q;
        #pragma unroll
        for (int i = 0; i < 7; i++)
            m[i] = mul2(s0p, *(const ull*)(u0 + 16 * i));
        om = 1.f - s0;
        if (q == 2) m[6] = pk2(om, 0.f);
    }

    DS_STEP(1, false, false);
    DS_STEP(2, false, true);
    #pragma unroll 1
    for (int k = 0; k < 15; k++) {
        int p = 3 + (k << 2);
        DS_STEP(p,     false, false);
        DS_STEP(p + 1, true,  false);
        DS_STEP(p + 2, false, false);
        DS_STEP(p + 3, false, true);
    }
    DS_STEP(63, false, false);

    // final exact normalization
    {
        ull ps = m[0];
        #pragma unroll
        for (int i = 1; i < 7; i++) ps = add2(ps, m[i]);
        float2 pv = upk2(ps);
        float fs = pv.x + pv.y;
        fs += __shfl_xor_sync(FULL, fs, 1);
        fs += __shfl_xor_sync(FULL, fs, 2);
        fs += __shfl_xor_sync(FULL, fs, 4);
        float rn = 1.f / fs;

        float* orow = sOut + r * 102;
        #pragma unroll
        for (int i = 0; i < 6; i++) {
            float2 mv = upk2(m[i]);
            int j = 2 * q + 16 * i;
            *(float2*)(orow + j) = make_float2(mv.x * rn, mv.y * rn);
        }
        float2 mv = upk2(m[6]);
        int j = 96 + 2 * q;
        if (q < 2)       *(float2*)(orow + j) = make_float2(mv.x * rn, mv.y * rn);
        else if (q == 2) orow[100] = mv.x * rn;
    }
    __syncthreads();

    for (int idx = tid; idx < 32 * (CDIM + 1); idx += 256) {
        int rr = idx / (CDIM + 1);
        int jj = idx - rr * (CDIM + 1);
        out[(size_t)r0 * (CDIM + 1) + idx] = sOut[rr * 102 + jj];
    }
}

extern "C" void kernel_launch(void* const* d_in, const int* in_sizes, int n_in,
                              void* d_out, int out_size) {
    const float* x    = (const float*)d_in[0];
    const float* w    = (const float*)d_in[1];
    const float* xi   = (const float*)d_in[2];
    const float* eta  = (const float*)d_in[3];
    const float* beta = (const float*)d_in[4];
    float* out = (float*)d_out;

    cudaFuncSetAttribute(gemm_si_kernel,
                         cudaFuncAttributeMaxDynamicSharedMemorySize, GSM_BYTES);
    cudaFuncSetAttribute(scan_kernel,
                         cudaFuncAttributeMaxDynamicSharedMemorySize, SSM_FLOATS * 4);

    gemm_si_kernel<<<BROWS / GROWS + 1, 128, GSM_BYTES>>>(x, w, xi, eta, beta);
    scan_kernel<<<BROWS / 32, 256, SSM_FLOATS * 4>>>(out);
}

// round 9
// speedup vs baseline: 1.3888x; 1.3888x over previous
#include <cuda_runtime.h>
#include <cstdint>
#include <math.h>

#define EPSV 1e-4f
#define BROWS 8192
#define FDIM 512
#define PDIM 64
#define CDIM 100
#define GROWS 32

typedef unsigned long long ull;

__device__ float g_si[BROWS * PDIM];
__device__ float g_u2[PDIM * 112];   // normalized beta^2, zero-padded rows

// ---- packed f32x2 helpers ----
__device__ __forceinline__ ull pk2(float lo, float hi) {
    ull r; asm("mov.b64 %0, {%1, %2};" : "=l"(r) : "f"(lo), "f"(hi)); return r;
}
__device__ __forceinline__ float2 upk2(ull v) {
    float2 r; asm("mov.b64 {%0, %1}, %2;" : "=f"(r.x), "=f"(r.y) : "l"(v)); return r;
}
__device__ __forceinline__ ull fma2(ull a, ull b, ull c) {
    ull d; asm("fma.rn.f32x2 %0, %1, %2, %3;" : "=l"(d) : "l"(a), "l"(b), "l"(c)); return d;
}
__device__ __forceinline__ ull mul2(ull a, ull b) {
    ull d; asm("mul.rn.f32x2 %0, %1, %2;" : "=l"(d) : "l"(a), "l"(b)); return d;
}
__device__ __forceinline__ ull add2(ull a, ull b) {
    ull d; asm("add.rn.f32x2 %0, %1, %2;" : "=l"(d) : "l"(a), "l"(b)); return d;
}
__device__ __forceinline__ float frcp(float x) {
    float r; asm("rcp.approx.f32 %0, %1;" : "=f"(r) : "f"(x)); return r;
}
__device__ __forceinline__ unsigned int s2u(const void* p) {
    return (unsigned int)__cvta_generic_to_shared(p);
}
__device__ __forceinline__ void cpa16(unsigned int dst, const void* src) {
    asm volatile("cp.async.cg.shared.global [%0], [%1], 16;" :: "r"(dst), "l"(src));
}

// ================= GEMM + si (R6 config: 64 threads, tile 4 rows x 8 protos) =====
__device__ __forceinline__ void stage_chunk(float* xsb, float* wsb,
                                            const float* __restrict__ x,
                                            const float* __restrict__ w,
                                            int r0, int kc, int tid) {
    #pragma unroll
    for (int it = 0; it < 8; it++) {
        int f = tid + it * 64;
        int row = f >> 4, c = f & 15;
        unsigned int dst = s2u(xsb + row * 64 + ((c * 4) ^ ((row >> 2) << 2)));
        cpa16(dst, x + (size_t)(r0 + row) * FDIM + kc + c * 4);
    }
    #pragma unroll
    for (int it = 0; it < 16; it++) {
        int f = tid + it * 64;
        int p = f >> 4, c = f & 15;
        unsigned int dst = s2u(wsb + p * 64 + ((c * 4) ^ ((p >> 3) << 2)));
        cpa16(dst, w + (size_t)p * FDIM + kc + c * 4);
    }
    asm volatile("cp.async.commit_group;" ::: "memory");
}

__global__ __launch_bounds__(64)
void gemm_si_kernel(const float* __restrict__ x, const float* __restrict__ w,
                    const float* __restrict__ xi, const float* __restrict__ eta,
                    const float* __restrict__ beta) {
    __shared__ __align__(16) float xs[2][GROWS * 64];   // 2 x 8 KB
    __shared__ __align__(16) float ws[2][PDIM * 64];    // 2 x 16 KB
    __shared__ float sWn[PDIM];

    const int tid = threadIdx.x;

    // block 0: compute u table once (wave-1 resident; consumed by next kernel)
    if (blockIdx.x == 0) {
        if (tid < PDIM) {
            const float* br = beta + (size_t)tid * CDIM;
            float* ur = g_u2 + tid * 112;
            float s2 = 0.f;
            #pragma unroll 4
            for (int c = 0; c < CDIM; c++) { float v = br[c]; float bb = v * v; ur[c] = bb; s2 += bb; }
            float rs = 1.f / s2;
            #pragma unroll 4
            for (int c = 0; c < CDIM; c++) ur[c] *= rs;
            #pragma unroll
            for (int c = CDIM; c < 112; c++) ur[c] = 0.f;
        }
        return;
    }

    const int r0  = (blockIdx.x - 1) * GROWS;
    const int rg  = tid >> 3;   // 0..7 : rows rg*4 + j
    const int pg  = tid & 7;    // 0..7 : protos pg*8 + i

    const int rw   = ((tid & 7) << 3) | (tid >> 3);
    const int xorW = (tid & 7) << 2;

    ull acc[4][8];
    #pragma unroll
    for (int j = 0; j < 4; j++)
        #pragma unroll
        for (int i = 0; i < 8; i++) acc[j][i] = 0ull;
    ull xn2[4] = {0ull, 0ull, 0ull, 0ull};
    ull wn2 = 0ull;

    stage_chunk(xs[0], ws[0], x, w, r0, 0, tid);

    #pragma unroll 1
    for (int ch = 0; ch < FDIM / 64; ch++) {
        const int buf = ch & 1;
        if (ch < FDIM / 64 - 1) {
            stage_chunk(xs[buf ^ 1], ws[buf ^ 1], x, w, r0, (ch + 1) * 64, tid);
            asm volatile("cp.async.wait_group 1;" ::: "memory");
        } else {
            asm volatile("cp.async.wait_group 0;" ::: "memory");
        }
        __syncthreads();

        const float* xb = xs[buf];
        const float* wb = ws[buf];

        {   // wnorm partials from staged w (thread owns proto rw)
            const float* wr = wb + (rw << 6);
            #pragma unroll
            for (int c = 0; c < 16; c++) {
                ulonglong2 v = *(const ulonglong2*)(wr + ((c * 4) ^ xorW));
                wn2 = fma2(v.x, v.x, wn2);
                wn2 = fma2(v.y, v.y, wn2);
            }
        }

        #pragma unroll
        for (int kk = 0; kk < 64; kk += 4) {
            ulonglong2 a2[4], b2[8];
            #pragma unroll
            for (int j = 0; j < 4; j++)
                a2[j] = *(const ulonglong2*)(xb + ((rg * 4 + j) << 6) + (kk ^ (rg << 2)));
            #pragma unroll
            for (int i = 0; i < 8; i++)
                b2[i] = *(const ulonglong2*)(wb + ((pg * 8 + i) << 6) + (kk ^ (pg << 2)));
            #pragma unroll
            for (int j = 0; j < 4; j++) {
                xn2[j] = fma2(a2[j].x, a2[j].x, xn2[j]);
                xn2[j] = fma2(a2[j].y, a2[j].y, xn2[j]);
                #pragma unroll
                for (int i = 0; i < 8; i++) {
                    acc[j][i] = fma2(a2[j].x, b2[i].x, acc[j][i]);
                    acc[j][i] = fma2(a2[j].y, b2[i].y, acc[j][i]);
                }
            }
        }
        __syncthreads();
    }

    { float2 v = upk2(wn2); sWn[rw] = v.x + v.y; }
    __syncthreads();

    float gam[8], alp[8], wnv[8];
    #pragma unroll
    for (int i = 0; i < 8; i++) {
        int p = pg * 8 + i;
        float e = __ldg(eta + p);
        gam[i] = e * e;
        alp[i] = 1.f / (1.f + __expf(-__ldg(xi + p)));
        wnv[i] = sWn[p];
    }

    const unsigned FULL = 0xffffffffu;
    #pragma unroll
    for (int j = 0; j < 4; j++) {
        const int row = rg * 4 + j;
        float2 xv = upk2(xn2[j]);
        const float xn = xv.x + xv.y;
        float sv[8];
        float mx = 0.f;
        #pragma unroll
        for (int i = 0; i < 8; i++) {
            float2 dv = upk2(acc[j][i]);
            float d = xn - 2.f * (dv.x + dv.y) + wnv[i];
            float si = __expf(-gam[i] * d) * alp[i];
            sv[i] = si;
            mx = fmaxf(mx, si);
        }
        mx = fmaxf(mx, __shfl_xor_sync(FULL, mx, 1));
        mx = fmaxf(mx, __shfl_xor_sync(FULL, mx, 2));
        mx = fmaxf(mx, __shfl_xor_sync(FULL, mx, 4));
        float inv = 1.f / (mx + EPSV);
        float4 o0, o1;
        o0.x = sv[0] * inv; o0.y = sv[1] * inv; o0.z = sv[2] * inv; o0.w = sv[3] * inv;
        o1.x = sv[4] * inv; o1.y = sv[5] * inv; o1.z = sv[6] * inv; o1.w = sv[7] * inv;
        *(float4*)(g_si + (size_t)(r0 + row) * PDIM + pg * 8)     = o0;
        *(float4*)(g_si + (size_t)(r0 + row) * PDIM + pg * 8 + 4) = o1;
    }
}

// ================= Dempster scan : 2 rows per 8-lane group, scalar omega ====
// Deferred normalization (rinv at p%4==2, folded into scalars at p%4==0).
// Omega lives ONLY in the per-lane scalar recurrence om' = 3*a*om; the vector
// slots past j=99 hold zeros (u pad = 0), so sums add om after the shfl tree.
#define SSM_FLOATS (7168 + 32 * 68 + 32 * 102)

#define DS_STEP(P, APPLY, START) do {                                          \
    float sA_ = srowA[(P)], sB_ = srowB[(P)];                                  \
    float aA_ = 1.f - sA_,  aB_ = 1.f - sB_;                                   \
    if (APPLY) { sA_ *= pendA; aA_ *= pendA; sB_ *= pendB; aB_ *= pendB; }     \
    float g1A_ = sA_ * omA, g1B_ = sB_ * omB;                                  \
    omA = 3.f * aA_ * omA;  omB = 3.f * aB_ * omB;                             \
    ull spA_ = pk2(sA_, sA_), apA_ = pk2(aA_, aA_), gpA_ = pk2(g1A_, g1A_);    \
    ull spB_ = pk2(sB_, sB_), apB_ = pk2(aB_, aB_), gpB_ = pk2(g1B_, g1B_);    \
    const float* up_ = sU + (P) * 112 + 2 * q;                                 \
    _Pragma("unroll")                                                          \
    for (int i_ = 0; i_ < 7; i_++) {                                           \
        ull u2_ = *(const ull*)(up_ + 16 * i_);                                \
        mA[i_] = fma2(gpA_, u2_, mul2(mA[i_], fma2(spA_, u2_, apA_)));         \
        mB[i_] = fma2(gpB_, u2_, mul2(mB[i_], fma2(spB_, u2_, apB_)));         \
    }                                                                          \
    if (START) {                                                               \
        ull psA_ = mA[0], psB_ = mB[0];                                        \
        _Pragma("unroll")                                                      \
        for (int i_ = 1; i_ < 7; i_++) { psA_ = add2(psA_, mA[i_]); psB_ = add2(psB_, mB[i_]); } \
        float2 va_ = upk2(psA_), vb_ = upk2(psB_);                             \
        float pa_ = va_.x + va_.y, pb_ = vb_.x + vb_.y;                        \
        pa_ += __shfl_xor_sync(FULL, pa_, 1); pb_ += __shfl_xor_sync(FULL, pb_, 1); \
        pa_ += __shfl_xor_sync(FULL, pa_, 2); pb_ += __shfl_xor_sync(FULL, pb_, 2); \
        pa_ += __shfl_xor_sync(FULL, pa_, 4); pb_ += __shfl_xor_sync(FULL, pb_, 4); \
        pendA = frcp(pa_ + omA); pendB = frcp(pb_ + omB);                      \
    }                                                                          \
} while (0)

__global__ __launch_bounds__(128)
void scan_kernel(float* __restrict__ out) {
    extern __shared__ __align__(16) float ssm[];
    float* sU   = ssm;                   // 7168 floats
    float* sSi  = ssm + 7168;            // 32 rows x stride 68
    float* sOut = ssm + 7168 + 32 * 68;  // 32 rows x stride 102

    const int tid = threadIdx.x;
    const int r0  = blockIdx.x * 32;
    const unsigned FULL = 0xffffffffu;

    #pragma unroll
    for (int it = 0; it < 14; it++) {
        int f = tid + it * 128;
        *(float4*)(sU + f * 4) = *(const float4*)(g_u2 + f * 4);
    }
    #pragma unroll
    for (int it = 0; it < 4; it++) {
        int f = tid + it * 128;
        int r = f >> 4, c = f & 15;
        *(float4*)(sSi + r * 68 + c * 4) =
            *(const float4*)(g_si + (size_t)(r0 + r) * PDIM + c * 4);
    }
    __syncthreads();

    const int lane = tid & 31;
    const int warp = tid >> 5;
    const int g = lane >> 3;           // group: 2 rows
    const int q = lane & 7;            // pairs j = 2q + 16i
    const int rA = warp * 8 + g * 2;
    const int rB = rA + 1;
    const float* srowA = sSi + rA * 68;
    const float* srowB = sSi + rB * 68;

    ull mA[7], mB[7];
    float omA, omB, pendA = 1.f, pendB = 1.f;
    {
        float s0A = srowA[0], s0B = srowB[0];
        ull sA0 = pk2(s0A, s0A), sB0 = pk2(s0B, s0B);
        const float* u0 = sU + 2 * q;
        #pragma unroll
        for (int i = 0; i < 7; i++) {
            ull u2 = *(const ull*)(u0 + 16 * i);
            mA[i] = mul2(sA0, u2);
            mB[i] = mul2(sB0, u2);
        }
        omA = 1.f - s0A; omB = 1.f - s0B;
    }

    DS_STEP(1, false, false);
    DS_STEP(2, false, true);
    #pragma unroll 1
    for (int k = 0; k < 15; k++) {
        int p = 3 + (k << 2);
        DS_STEP(p,     false, false);
        DS_STEP(p + 1, true,  false);
        DS_STEP(p + 2, false, false);
        DS_STEP(p + 3, false, true);
    }
    DS_STEP(63, false, false);

    // final exact normalization (omega added as scalar)
    {
        ull psA = mA[0], psB = mB[0];
        #pragma unroll
        for (int i = 1; i < 7; i++) { psA = add2(psA, mA[i]); psB = add2(psB, mB[i]); }
        float2 va = upk2(psA), vb = upk2(psB);
        float fa = va.x + va.y, fb = vb.x + vb.y;
        fa += __shfl_xor_sync(FULL, fa, 1); fb += __shfl_xor_sync(FULL, fb, 1);
        fa += __shfl_xor_sync(FULL, fa, 2); fb += __shfl_xor_sync(FULL, fb, 2);
        fa += __shfl_xor_sync(FULL, fa, 4); fb += __shfl_xor_sync(FULL, fb, 4);
        float rnA = 1.f / (fa + omA), rnB = 1.f / (fb + omB);

        float* oA = sOut + rA * 102;
        float* oB = sOut + rB * 102;
        #pragma unroll
        for (int i = 0; i < 6; i++) {
            int j = 2 * q + 16 * i;
            float2 a = upk2(mA[i]), b = upk2(mB[i]);
            *(float2*)(oA + j) = make_float2(a.x * rnA, a.y * rnA);
            *(float2*)(oB + j) = make_float2(b.x * rnB, b.y * rnB);
        }
        int j = 96 + 2 * q;
        if (q < 2) {
            float2 a = upk2(mA[6]), b = upk2(mB[6]);
            *(float2*)(oA + j) = make_float2(a.x * rnA, a.y * rnA);
            *(float2*)(oB + j) = make_float2(b.x * rnB, b.y * rnB);
        } else if (q == 2) {
            oA[100] = omA * rnA;
            oB[100] = omB * rnB;
        }
    }
    __syncthreads();

    for (int idx = tid; idx < 32 * (CDIM + 1); idx += 128) {
        int rr = idx / (CDIM + 1);
        int jj = idx - rr * (CDIM + 1);
        out[(size_t)r0 * (CDIM + 1) + idx] = sOut[rr * 102 + jj];
    }
}

extern "C" void kernel_launch(void* const* d_in, const int* in_sizes, int n_in,
                              void* d_out, int out_size) {
    const float* x    = (const float*)d_in[0];
    const float* w    = (const float*)d_in[1];
    const float* xi   = (const float*)d_in[2];
    const float* eta  = (const float*)d_in[3];
    const float* beta = (const float*)d_in[4];
    float* out = (float*)d_out;

    cudaFuncSetAttribute(scan_kernel,
                         cudaFuncAttributeMaxDynamicSharedMemorySize, SSM_FLOATS * 4);

    gemm_si_kernel<<<BROWS / GROWS + 1, 64>>>(x, w, xi, eta, beta);
    scan_kernel<<<BROWS / 32, 128, SSM_FLOATS * 4>>>(out);
}